// round 2
// baseline (speedup 1.0000x reference)
#include <cuda_runtime.h>

// PosController_Vectorized: elementwise PID + yaw rotation + clamping over N drones.
// Pure streaming: 17 floats in, 3 floats out per drone. HBM-bound (R1: 6.43 TB/s eff).
// R2: streaming cache hints (__ldcs/__stcs) + occupancy bump via launch_bounds(256,4).

#ifndef PC_N
#define PC_N 4194304
#endif

__global__ __launch_bounds__(256, 4)
void pos_controller_kernel(const float4* __restrict__ ref_ve,
                           const float4* __restrict__ meas_ve,
                           const float4* __restrict__ meas_yaw,
                           const float4* __restrict__ mass,
                           const float4* __restrict__ pid_int,
                           const float4* __restrict__ pid_prev_err,
                           const float4* __restrict__ pid_prev_d,
                           float4* __restrict__ rp_out,
                           float4* __restrict__ thr_out)
{
    const int t = blockIdx.x * blockDim.x + threadIdx.x;   // each thread: 4 drones
    const int nt = PC_N / 4;
    if (t >= nt) return;

    const float G = 9.81f;
    const float DT = 1.0f / 100.0f;
    const float INV_DT = 100.0f;
    const float TAU = 0.05f;
    const float ALPHA = DT / (TAU + DT);
    const float MAX_THRUST = 0.9f * 44.4f;
    const float MAX_ANGLE = 30.0f * 3.14159265358979323846f / 180.0f;
    const float INV_G = 1.0f / G;
    const float LIM = 6.0f;

    // Issue ALL loads up front with evict-first policy (single-use data).
    float4 rv0 = __ldcs(&ref_ve[3*t+0]);
    float4 rv1 = __ldcs(&ref_ve[3*t+1]);
    float4 rv2 = __ldcs(&ref_ve[3*t+2]);
    float4 mv0 = __ldcs(&meas_ve[3*t+0]);
    float4 mv1 = __ldcs(&meas_ve[3*t+1]);
    float4 mv2 = __ldcs(&meas_ve[3*t+2]);
    float4 pi0 = __ldcs(&pid_int[3*t+0]);
    float4 pi1 = __ldcs(&pid_int[3*t+1]);
    float4 pi2 = __ldcs(&pid_int[3*t+2]);
    float4 pe0 = __ldcs(&pid_prev_err[3*t+0]);
    float4 pe1 = __ldcs(&pid_prev_err[3*t+1]);
    float4 pe2 = __ldcs(&pid_prev_err[3*t+2]);
    float4 pd0 = __ldcs(&pid_prev_d[3*t+0]);
    float4 pd1 = __ldcs(&pid_prev_d[3*t+1]);
    float4 pd2 = __ldcs(&pid_prev_d[3*t+2]);
    float4 yw  = __ldcs(&meas_yaw[t]);
    float4 ms  = __ldcs(&mass[t]);

    // View as flat lanes: index k = drone*3 + axis, for k in [0,12)
    float e[12], I[12], Pe[12], Pd[12];
    {
        const float* rvf = &rv0.x;  // rv0..rv2 contiguous in regs? Not guaranteed —
        // use explicit copies instead to stay well-defined:
        float rvv[12] = {rv0.x,rv0.y,rv0.z,rv0.w, rv1.x,rv1.y,rv1.z,rv1.w, rv2.x,rv2.y,rv2.z,rv2.w};
        float mvv[12] = {mv0.x,mv0.y,mv0.z,mv0.w, mv1.x,mv1.y,mv1.z,mv1.w, mv2.x,mv2.y,mv2.z,mv2.w};
        float piv[12] = {pi0.x,pi0.y,pi0.z,pi0.w, pi1.x,pi1.y,pi1.z,pi1.w, pi2.x,pi2.y,pi2.z,pi2.w};
        float pev[12] = {pe0.x,pe0.y,pe0.z,pe0.w, pe1.x,pe1.y,pe1.z,pe1.w, pe2.x,pe2.y,pe2.z,pe2.w};
        float pdv[12] = {pd0.x,pd0.y,pd0.z,pd0.w, pd1.x,pd1.y,pd1.z,pd1.w, pd2.x,pd2.y,pd2.z,pd2.w};
        (void)rvf;
        #pragma unroll
        for (int k = 0; k < 12; ++k) {
            e[k]  = rvv[k] - mvv[k];
            I[k]  = piv[k];
            Pe[k] = pev[k];
            Pd[k] = pdv[k];
        }
    }

    const float ywf[4] = {yw.x, yw.y, yw.z, yw.w};
    const float msf[4] = {ms.x, ms.y, ms.z, ms.w};
    const float KPv[3] = {2.0f, 2.0f, 4.0f};
    const float KIv[3] = {0.5f, 0.5f, 1.0f};
    const float KDv[3] = {0.1f, 0.1f, 0.05f};

    float rp[8], thr[4];

    #pragma unroll
    for (int i = 0; i < 4; ++i) {
        float u[3];
        #pragma unroll
        for (int ax = 0; ax < 3; ++ax) {
            const int k = i * 3 + ax;
            const float err   = e[k];
            const float integ = I[k] + err * DT;
            const float d_raw = (err - Pe[k]) * INV_DT;
            const float d     = Pd[k] + ALPHA * (d_raw - Pd[k]);
            float uu = KPv[ax] * err + KIv[ax] * integ + KDv[ax] * d;
            u[ax] = fminf(fmaxf(uu, -LIM), LIM);
        }

        float sy, cy;
        sincosf(ywf[i], &sy, &cy);

        const float rp0 = (sy * u[0] - cy * u[1]) * INV_G;
        const float rp1 = (cy * u[0] + sy * u[1]) * INV_G;

        const float mag = sqrtf(rp0 * rp0 + rp1 * rp1);
        const float s = (mag > MAX_ANGLE) ? fminf(MAX_ANGLE / (mag + 1e-6f), 1.0f) : 1.0f;

        rp[2*i]   = rp0 * s;
        rp[2*i+1] = rp1 * s;

        const float m  = msf[i];
        const float tr = m * G + m * u[2];
        thr[i] = fminf(fmaxf(tr, 0.8f * G * m), MAX_THRUST);
    }

    __stcs(&rp_out[2*t],     make_float4(rp[0], rp[1], rp[2], rp[3]));
    __stcs(&rp_out[2*t+1],   make_float4(rp[4], rp[5], rp[6], rp[7]));
    __stcs(&thr_out[t],      make_float4(thr[0], thr[1], thr[2], thr[3]));
}

extern "C" void kernel_launch(void* const* d_in, const int* in_sizes, int n_in,
                              void* d_out, int out_size)
{
    const float4* ref_ve       = (const float4*)d_in[0];
    const float4* meas_ve      = (const float4*)d_in[1];
    const float4* meas_yaw     = (const float4*)d_in[2];
    const float4* mass         = (const float4*)d_in[3];
    const float4* pid_int      = (const float4*)d_in[4];
    const float4* pid_prev_err = (const float4*)d_in[5];
    const float4* pid_prev_d   = (const float4*)d_in[6];

    float* out = (float*)d_out;
    float4* rp_out  = (float4*)out;
    float4* thr_out = (float4*)(out + 2 * (size_t)PC_N);

    const int threads = 256;
    const int nt = PC_N / 4;
    const int blocks = (nt + threads - 1) / threads;
    pos_controller_kernel<<<blocks, threads>>>(ref_ve, meas_ve, meas_yaw, mass,
                                               pid_int, pid_prev_err, pid_prev_d,
                                               rp_out, thr_out);
}

// round 3
// speedup vs baseline: 1.4516x; 1.4516x over previous
#include <cuda_runtime.h>

// PosController_Vectorized: elementwise PID + yaw rotation + clamping over N drones.
// Pure streaming: 17 floats in, 3 floats out per drone. HBM-bound.
// R1: 49.8us kernel, DRAM 82.2%, regs=80.
// R2 FAILED: launch_bounds(256,4) reg cap -> spills (L1 48%) -> 68.4us. Reverted.
// R3: R1 config + __ldcs/__stcs streaming hints ONLY (isolated A/B).

#ifndef PC_N
#define PC_N 4194304
#endif

__global__ __launch_bounds__(256)
void pos_controller_kernel(const float4* __restrict__ ref_ve,
                           const float4* __restrict__ meas_ve,
                           const float4* __restrict__ meas_yaw,
                           const float4* __restrict__ mass,
                           const float4* __restrict__ pid_int,
                           const float4* __restrict__ pid_prev_err,
                           const float4* __restrict__ pid_prev_d,
                           float4* __restrict__ rp_out,
                           float4* __restrict__ thr_out)
{
    const int t = blockIdx.x * blockDim.x + threadIdx.x;   // each thread: 4 drones
    const int nt = PC_N / 4;
    if (t >= nt) return;

    const float G = 9.81f;
    const float DT = 1.0f / 100.0f;
    const float INV_DT = 100.0f;
    const float TAU = 0.05f;
    const float ALPHA = DT / (TAU + DT);
    const float MAX_THRUST = 0.9f * 44.4f;
    const float MAX_ANGLE = 30.0f * 3.14159265358979323846f / 180.0f;
    const float INV_G = 1.0f / G;
    const float LIM = 6.0f;

    // All loads up front, evict-first (single-use data).
    float4 rv0 = __ldcs(&ref_ve[3*t+0]);
    float4 rv1 = __ldcs(&ref_ve[3*t+1]);
    float4 rv2 = __ldcs(&ref_ve[3*t+2]);
    float4 mv0 = __ldcs(&meas_ve[3*t+0]);
    float4 mv1 = __ldcs(&meas_ve[3*t+1]);
    float4 mv2 = __ldcs(&meas_ve[3*t+2]);
    float4 pi0 = __ldcs(&pid_int[3*t+0]);
    float4 pi1 = __ldcs(&pid_int[3*t+1]);
    float4 pi2 = __ldcs(&pid_int[3*t+2]);
    float4 pe0 = __ldcs(&pid_prev_err[3*t+0]);
    float4 pe1 = __ldcs(&pid_prev_err[3*t+1]);
    float4 pe2 = __ldcs(&pid_prev_err[3*t+2]);
    float4 pd0 = __ldcs(&pid_prev_d[3*t+0]);
    float4 pd1 = __ldcs(&pid_prev_d[3*t+1]);
    float4 pd2 = __ldcs(&pid_prev_d[3*t+2]);
    float4 yw  = __ldcs(&meas_yaw[t]);
    float4 ms  = __ldcs(&mass[t]);

    float e[12], I[12], Pe[12], Pd[12];
    {
        float rvv[12] = {rv0.x,rv0.y,rv0.z,rv0.w, rv1.x,rv1.y,rv1.z,rv1.w, rv2.x,rv2.y,rv2.z,rv2.w};
        float mvv[12] = {mv0.x,mv0.y,mv0.z,mv0.w, mv1.x,mv1.y,mv1.z,mv1.w, mv2.x,mv2.y,mv2.z,mv2.w};
        float piv[12] = {pi0.x,pi0.y,pi0.z,pi0.w, pi1.x,pi1.y,pi1.z,pi1.w, pi2.x,pi2.y,pi2.z,pi2.w};
        float pev[12] = {pe0.x,pe0.y,pe0.z,pe0.w, pe1.x,pe1.y,pe1.z,pe1.w, pe2.x,pe2.y,pe2.z,pe2.w};
        float pdv[12] = {pd0.x,pd0.y,pd0.z,pd0.w, pd1.x,pd1.y,pd1.z,pd1.w, pd2.x,pd2.y,pd2.z,pd2.w};
        #pragma unroll
        for (int k = 0; k < 12; ++k) {
            e[k]  = rvv[k] - mvv[k];
            I[k]  = piv[k];
            Pe[k] = pev[k];
            Pd[k] = pdv[k];
        }
    }

    const float ywf[4] = {yw.x, yw.y, yw.z, yw.w};
    const float msf[4] = {ms.x, ms.y, ms.z, ms.w};
    const float KPv[3] = {2.0f, 2.0f, 4.0f};
    const float KIv[3] = {0.5f, 0.5f, 1.0f};
    const float KDv[3] = {0.1f, 0.1f, 0.05f};

    float rp[8], thr[4];

    #pragma unroll
    for (int i = 0; i < 4; ++i) {
        float u[3];
        #pragma unroll
        for (int ax = 0; ax < 3; ++ax) {
            const int k = i * 3 + ax;
            const float err   = e[k];
            const float integ = I[k] + err * DT;
            const float d_raw = (err - Pe[k]) * INV_DT;
            const float d     = Pd[k] + ALPHA * (d_raw - Pd[k]);
            float uu = KPv[ax] * err + KIv[ax] * integ + KDv[ax] * d;
            u[ax] = fminf(fmaxf(uu, -LIM), LIM);
        }

        float sy, cy;
        sincosf(ywf[i], &sy, &cy);

        const float rp0 = (sy * u[0] - cy * u[1]) * INV_G;
        const float rp1 = (cy * u[0] + sy * u[1]) * INV_G;

        const float mag = sqrtf(rp0 * rp0 + rp1 * rp1);
        const float s = (mag > MAX_ANGLE) ? fminf(MAX_ANGLE / (mag + 1e-6f), 1.0f) : 1.0f;

        rp[2*i]   = rp0 * s;
        rp[2*i+1] = rp1 * s;

        const float m  = msf[i];
        const float tr = m * G + m * u[2];
        thr[i] = fminf(fmaxf(tr, 0.8f * G * m), MAX_THRUST);
    }

    __stcs(&rp_out[2*t],   make_float4(rp[0], rp[1], rp[2], rp[3]));
    __stcs(&rp_out[2*t+1], make_float4(rp[4], rp[5], rp[6], rp[7]));
    __stcs(&thr_out[t],    make_float4(thr[0], thr[1], thr[2], thr[3]));
}

extern "C" void kernel_launch(void* const* d_in, const int* in_sizes, int n_in,
                              void* d_out, int out_size)
{
    const float4* ref_ve       = (const float4*)d_in[0];
    const float4* meas_ve      = (const float4*)d_in[1];
    const float4* meas_yaw     = (const float4*)d_in[2];
    const float4* mass         = (const float4*)d_in[3];
    const float4* pid_int      = (const float4*)d_in[4];
    const float4* pid_prev_err = (const float4*)d_in[5];
    const float4* pid_prev_d   = (const float4*)d_in[6];

    float* out = (float*)d_out;
    float4* rp_out  = (float4*)out;
    float4* thr_out = (float4*)(out + 2 * (size_t)PC_N);

    const int threads = 256;
    const int nt = PC_N / 4;
    const int blocks = (nt + threads - 1) / threads;
    pos_controller_kernel<<<blocks, threads>>>(ref_ve, meas_ve, meas_yaw, mass,
                                               pid_int, pid_prev_err, pid_prev_d,
                                               rp_out, thr_out);
}